// round 1
// baseline (speedup 1.0000x reference)
#include <cuda_runtime.h>
#include <cuda_bf16.h>

// Problem constants (fixed by setup_inputs): T=128, N=2048, D=256, w=3
#define T_SNAP 128
#define N_NODE 2048
#define D_HID  256
#define WIN    3
#define ROWS   (T_SNAP * N_NODE)   // 262144

// Scratch (allocation-free rule: __device__ globals)
__device__ float g_score[ROWS];
__device__ float g_p[ROWS];

// ---------------------------------------------------------------------------
// Kernel 1: score[j*N+n] = proj . tanh( X[j,n,:] @ W )
// X viewed as (ROWS, 256) row-major; W (256,256) row-major [k][e].
// Block tile: 64 rows x 256 cols (full D), BK=32. 256 threads, 8x8/thread.
// ---------------------------------------------------------------------------
__global__ __launch_bounds__(256) void score_kernel(
    const float* __restrict__ X,
    const float* __restrict__ W,
    const float* __restrict__ proj)
{
    __shared__ float As[64 * 32];    // [m][k]  (8 KB)
    __shared__ float Bs[32 * 256];   // [k][col] (32 KB)

    const int tid = threadIdx.x;
    const int tx  = tid & 31;        // lane
    const int ty  = tid >> 5;        // warp 0..7 -> row group
    const int row0 = blockIdx.x * 64;

    float acc[8][8];
    #pragma unroll
    for (int r = 0; r < 8; r++)
        #pragma unroll
        for (int j = 0; j < 8; j++) acc[r][j] = 0.0f;

    const float4* X4 = reinterpret_cast<const float4*>(X);
    const float4* W4 = reinterpret_cast<const float4*>(W);
    float4* As4 = reinterpret_cast<float4*>(As);
    float4* Bs4 = reinterpret_cast<float4*>(Bs);

    for (int k0 = 0; k0 < 256; k0 += 32) {
        // Load A tile: 64 rows x 32 k = 512 float4, 2 per thread (coalesced)
        #pragma unroll
        for (int i = 0; i < 2; i++) {
            int l4 = tid + i * 256;
            int m  = l4 >> 3;
            int kc = l4 & 7;
            As4[l4] = X4[(row0 + m) * 64 + (k0 >> 2) + kc];
        }
        // Load B tile: 32 k x 256 cols = 2048 float4, 8 per thread (coalesced)
        #pragma unroll
        for (int i = 0; i < 8; i++) {
            int l4 = tid + i * 256;
            int kk = l4 >> 6;
            int c4 = l4 & 63;
            Bs4[l4] = W4[(k0 + kk) * 64 + c4];
        }
        __syncthreads();

        #pragma unroll
        for (int kk = 0; kk < 32; kk++) {
            float4 b0 = Bs4[kk * 64 + tx];       // cols tx*4 .. tx*4+3
            float4 b1 = Bs4[kk * 64 + 32 + tx];  // cols 128+tx*4 .. +3
            float b[8] = {b0.x, b0.y, b0.z, b0.w, b1.x, b1.y, b1.z, b1.w};
            #pragma unroll
            for (int r = 0; r < 8; r++) {
                float a = As[(ty * 8 + r) * 32 + kk];  // broadcast within warp
                #pragma unroll
                for (int j = 0; j < 8; j++)
                    acc[r][j] = fmaf(a, b[j], acc[r][j]);
            }
        }
        __syncthreads();
    }

    // Fused epilogue: partial[r] = sum_j tanh(acc[r][j]) * proj[col(j)]
    float partial[8];
    #pragma unroll
    for (int r = 0; r < 8; r++) partial[r] = 0.0f;
    #pragma unroll
    for (int j = 0; j < 8; j++) {
        int c = (j < 4) ? (tx * 4 + j) : (128 + tx * 4 + (j - 4));
        float pj = proj[c];
        #pragma unroll
        for (int r = 0; r < 8; r++)
            partial[r] += tanhf(acc[r][j]) * pj;
    }
    // Warp reduce across the 32 column-lanes (all lanes of warp ty share rows)
    #pragma unroll
    for (int off = 16; off > 0; off >>= 1)
        #pragma unroll
        for (int r = 0; r < 8; r++)
            partial[r] += __shfl_xor_sync(0xffffffffu, partial[r], off);
    if (tx == 0) {
        #pragma unroll
        for (int r = 0; r < 8; r++)
            g_score[row0 + ty * 8 + r] = partial[r];
    }
}

// ---------------------------------------------------------------------------
// Kernel 2: p[j,:] = softmax over N of score[j,:]   (one block per row j)
// ---------------------------------------------------------------------------
__global__ __launch_bounds__(256) void softmax_kernel()
{
    __shared__ float red_max[8];
    __shared__ float red_sum[8];
    const int j   = blockIdx.x;
    const int tid = threadIdx.x;
    const float* row = g_score + j * N_NODE;

    float v[8];
    float m = -1e30f;
    #pragma unroll
    for (int i = 0; i < 8; i++) {
        v[i] = row[tid + i * 256];
        m = fmaxf(m, v[i]);
    }
    #pragma unroll
    for (int off = 16; off > 0; off >>= 1)
        m = fmaxf(m, __shfl_xor_sync(0xffffffffu, m, off));
    if ((tid & 31) == 0) red_max[tid >> 5] = m;
    __syncthreads();
    float bm = red_max[0];
    #pragma unroll
    for (int wq = 1; wq < 8; wq++) bm = fmaxf(bm, red_max[wq]);

    float s = 0.0f;
    #pragma unroll
    for (int i = 0; i < 8; i++) {
        v[i] = expf(v[i] - bm);
        s += v[i];
    }
    #pragma unroll
    for (int off = 16; off > 0; off >>= 1)
        s += __shfl_xor_sync(0xffffffffu, s, off);
    if ((tid & 31) == 0) red_sum[tid >> 5] = s;
    __syncthreads();
    float bs = 0.0f;
    #pragma unroll
    for (int wq = 0; wq < 8; wq++) bs += red_sum[wq];
    float inv = 1.0f / bs;

    #pragma unroll
    for (int i = 0; i < 8; i++)
        g_p[j * N_NODE + tid + i * 256] = v[i] * inv;
}

// ---------------------------------------------------------------------------
// Kernel 3: out[i,n,:] = X[i,n,:] for i<3, else
//           sum_{k=1..3} p[i-k,n] * X[i-k,n,:]    (float4-vectorized stream)
// ---------------------------------------------------------------------------
__global__ __launch_bounds__(256) void out_kernel(
    const float4* __restrict__ X4,
    float4* __restrict__ out4)
{
    const int STRIDE_T = N_NODE * (D_HID / 4);  // float4 per snapshot = 131072
    int idx = blockIdx.x * 256 + threadIdx.x;   // total 16777216
    int n = (idx >> 6) & (N_NODE - 1);
    int i = idx >> 17;

    if (i < WIN) {
        out4[idx] = X4[idx];
    } else {
        int base = (i - 3) * N_NODE + n;
        float p0 = g_p[base];
        float p1 = g_p[base + N_NODE];
        float p2 = g_p[base + 2 * N_NODE];
        float4 a = X4[idx - 3 * STRIDE_T];
        float4 b = X4[idx - 2 * STRIDE_T];
        float4 c = X4[idx - 1 * STRIDE_T];
        float4 o;
        o.x = p0 * a.x + p1 * b.x + p2 * c.x;
        o.y = p0 * a.y + p1 * b.y + p2 * c.y;
        o.z = p0 * a.z + p1 * b.z + p2 * c.z;
        o.w = p0 * a.w + p1 * b.w + p2 * c.w;
        out4[idx] = o;
    }
}

// ---------------------------------------------------------------------------
extern "C" void kernel_launch(void* const* d_in, const int* in_sizes, int n_in,
                              void* d_out, int out_size)
{
    const float* X    = (const float*)d_in[0];  // (128, 2048, 256)
    const float* W    = (const float*)d_in[1];  // (256, 256)
    const float* proj = (const float*)d_in[2];  // (256, 1)
    float* out        = (float*)d_out;

    score_kernel<<<ROWS / 64, 256>>>(X, W, proj);
    softmax_kernel<<<T_SNAP, 256>>>();
    out_kernel<<<(ROWS * (D_HID / 4)) / 256, 256>>>(
        (const float4*)X, (float4*)out);
}

// round 3
// speedup vs baseline: 2.4462x; 2.4462x over previous
#include <cuda_runtime.h>
#include <cstdint>

// Problem constants (fixed by setup_inputs): T=128, N=2048, D=256, w=3
#define T_SNAP 128
#define N_NODE 2048
#define D_HID  256
#define WIN    3
#define ROWS   (T_SNAP * N_NODE)   // 262144

// Scratch (allocation-free rule: __device__ globals)
__device__ float g_score[ROWS];
__device__ float g_p[ROWS];

// ---------------------------------------------------------------------------
__device__ __forceinline__ uint32_t to_tf32(float x) {
    uint32_t u;
    asm("cvt.rna.tf32.f32 %0, %1;" : "=r"(u) : "f"(x));
    return u;
}

__device__ __forceinline__ void mma_tf32(float* c, const uint32_t* a, const uint32_t* b) {
    asm volatile(
        "mma.sync.aligned.m16n8k8.row.col.f32.tf32.tf32.f32 "
        "{%0,%1,%2,%3}, {%4,%5,%6,%7}, {%8,%9}, {%0,%1,%2,%3};"
        : "+f"(c[0]), "+f"(c[1]), "+f"(c[2]), "+f"(c[3])
        : "r"(a[0]), "r"(a[1]), "r"(a[2]), "r"(a[3]), "r"(b[0]), "r"(b[1]));
}

// ---------------------------------------------------------------------------
// Kernel 1 (mma.sync tf32): score[row] = proj . tanh( X[row,:] @ W )
// Block: 256 threads = 8 warps in 2(M) x 4(N). Block tile M=64, N=256, BK=32.
// Warp tile 32x64 = 2x8 m16n8k8 mma per k-step. Epilogue fused (tanh, proj
// dot, quad-shuffle + cross-warp reduce).
// ---------------------------------------------------------------------------
#define AS_STRIDE 36    // floats; bank = (4*row+col)%32 -> conflict-free A frags
#define BS_STRIDE 264   // floats; bank = (8*k+n)%32   -> conflict-free B frags

__global__ __launch_bounds__(256, 2) void score_kernel(
    const float4* __restrict__ X4,
    const float4* __restrict__ W4,
    const float*  __restrict__ proj)
{
    __shared__ float As[64 * AS_STRIDE];       // ~9.2 KB
    __shared__ float Bs[32 * BS_STRIDE];       // ~33.8 KB
    __shared__ float sproj[D_HID];
    __shared__ float part[4][64];

    const int tid    = threadIdx.x;
    const int lane   = tid & 31;
    const int wid    = tid >> 5;
    const int warp_m = wid >> 2;               // 0..1
    const int warp_n = wid & 3;                // 0..3
    const int qid    = lane >> 2;              // 0..7 (group)
    const int qlane  = lane & 3;               // 0..3 (thread in group)
    const int row0   = blockIdx.x * 64;

    sproj[tid] = proj[tid];

    float acc[2][8][4];
    #pragma unroll
    for (int mt = 0; mt < 2; mt++)
        #pragma unroll
        for (int nt = 0; nt < 8; nt++)
            #pragma unroll
            for (int i = 0; i < 4; i++) acc[mt][nt][i] = 0.0f;

    #pragma unroll 1
    for (int c = 0; c < 8; ++c) {
        // Load A chunk: 64 rows x 32 k (512 float4, 2/thread, coalesced)
        #pragma unroll
        for (int i = 0; i < 2; i++) {
            int l4 = tid + i * 256;
            int m  = l4 >> 3;
            int c4 = l4 & 7;
            float4 v = X4[(row0 + m) * 64 + c * 8 + c4];
            uint4 t;
            t.x = to_tf32(v.x); t.y = to_tf32(v.y);
            t.z = to_tf32(v.z); t.w = to_tf32(v.w);
            *reinterpret_cast<uint4*>(&As[m * AS_STRIDE + c4 * 4]) = t;
        }
        // Load B chunk: 32 k x 256 n (2048 float4, 8/thread, coalesced)
        #pragma unroll
        for (int i = 0; i < 8; i++) {
            int l4 = tid + i * 256;
            int k  = l4 >> 6;
            int c4 = l4 & 63;
            float4 v = W4[(c * 32 + k) * 64 + c4];
            uint4 t;
            t.x = to_tf32(v.x); t.y = to_tf32(v.y);
            t.z = to_tf32(v.z); t.w = to_tf32(v.w);
            *reinterpret_cast<uint4*>(&Bs[k * BS_STRIDE + c4 * 4]) = t;
        }
        __syncthreads();

        #pragma unroll
        for (int ks = 0; ks < 4; ks++) {
            const int kk = ks * 8;
            // A fragments: 2 m-tiles x 4 regs
            uint32_t a[2][4];
            #pragma unroll
            for (int mt = 0; mt < 2; mt++) {
                int r = warp_m * 32 + mt * 16 + qid;
                const uint32_t* Au = reinterpret_cast<const uint32_t*>(As);
                a[mt][0] = Au[r * AS_STRIDE + kk + qlane];
                a[mt][1] = Au[(r + 8) * AS_STRIDE + kk + qlane];
                a[mt][2] = Au[r * AS_STRIDE + kk + qlane + 4];
                a[mt][3] = Au[(r + 8) * AS_STRIDE + kk + qlane + 4];
            }
            // B fragments: 8 n-tiles x 2 regs
            uint32_t b[8][2];
            #pragma unroll
            for (int nt = 0; nt < 8; nt++) {
                int n = warp_n * 64 + nt * 8 + qid;
                const uint32_t* Bu = reinterpret_cast<const uint32_t*>(Bs);
                b[nt][0] = Bu[(kk + qlane) * BS_STRIDE + n];
                b[nt][1] = Bu[(kk + qlane + 4) * BS_STRIDE + n];
            }
            #pragma unroll
            for (int mt = 0; mt < 2; mt++)
                #pragma unroll
                for (int nt = 0; nt < 8; nt++)
                    mma_tf32(acc[mt][nt], a[mt], b[nt]);
        }
        __syncthreads();
    }

    // Fused epilogue: per-row sum of tanh(u)*proj over this warp's 64 cols.
    // Thread owns cols 2*qlane, 2*qlane+1 of each n-tile; rows qid, qid+8.
    float psum[2][2];
    psum[0][0] = psum[0][1] = psum[1][0] = psum[1][1] = 0.0f;
    #pragma unroll
    for (int mt = 0; mt < 2; mt++)
        #pragma unroll
        for (int nt = 0; nt < 8; nt++) {
            int cb = warp_n * 64 + nt * 8 + 2 * qlane;
            float p0 = sproj[cb], p1 = sproj[cb + 1];
            psum[mt][0] += tanhf(acc[mt][nt][0]) * p0 + tanhf(acc[mt][nt][1]) * p1;
            psum[mt][1] += tanhf(acc[mt][nt][2]) * p0 + tanhf(acc[mt][nt][3]) * p1;
        }
    // Reduce across the 4 quad lanes (they cover the 8 cols of each n-tile)
    #pragma unroll
    for (int off = 1; off < 4; off <<= 1) {
        #pragma unroll
        for (int mt = 0; mt < 2; mt++) {
            psum[mt][0] += __shfl_xor_sync(0xffffffffu, psum[mt][0], off);
            psum[mt][1] += __shfl_xor_sync(0xffffffffu, psum[mt][1], off);
        }
    }
    if (qlane == 0) {
        #pragma unroll
        for (int mt = 0; mt < 2; mt++) {
            part[warp_n][warp_m * 32 + mt * 16 + qid]     = psum[mt][0];
            part[warp_n][warp_m * 32 + mt * 16 + qid + 8] = psum[mt][1];
        }
    }
    __syncthreads();
    if (tid < 64)
        g_score[row0 + tid] =
            part[0][tid] + part[1][tid] + part[2][tid] + part[3][tid];
}

// ---------------------------------------------------------------------------
// Kernel 2: p[j,:] = softmax over N of score[j,:]   (one block per row j)
// ---------------------------------------------------------------------------
__global__ __launch_bounds__(256) void softmax_kernel()
{
    __shared__ float red_max[8];
    __shared__ float red_sum[8];
    const int j   = blockIdx.x;
    const int tid = threadIdx.x;
    const float* row = g_score + j * N_NODE;

    float v[8];
    float m = -1e30f;
    #pragma unroll
    for (int i = 0; i < 8; i++) {
        v[i] = row[tid + i * 256];
        m = fmaxf(m, v[i]);
    }
    #pragma unroll
    for (int off = 16; off > 0; off >>= 1)
        m = fmaxf(m, __shfl_xor_sync(0xffffffffu, m, off));
    if ((tid & 31) == 0) red_max[tid >> 5] = m;
    __syncthreads();
    float bm = red_max[0];
    #pragma unroll
    for (int wq = 1; wq < 8; wq++) bm = fmaxf(bm, red_max[wq]);

    float s = 0.0f;
    #pragma unroll
    for (int i = 0; i < 8; i++) {
        v[i] = expf(v[i] - bm);
        s += v[i];
    }
    #pragma unroll
    for (int off = 16; off > 0; off >>= 1)
        s += __shfl_xor_sync(0xffffffffu, s, off);
    if ((tid & 31) == 0) red_sum[tid >> 5] = s;
    __syncthreads();
    float bs = 0.0f;
    #pragma unroll
    for (int wq = 0; wq < 8; wq++) bs += red_sum[wq];
    float inv = 1.0f / bs;

    #pragma unroll
    for (int i = 0; i < 8; i++)
        g_p[j * N_NODE + tid + i * 256] = v[i] * inv;
}

// ---------------------------------------------------------------------------
// Kernel 3: out[i,n,:] = X[i,n,:] for i<3, else
//           sum_{k=1..3} p[i-k,n] * X[i-k,n,:]    (float4-vectorized stream)
// ---------------------------------------------------------------------------
__global__ __launch_bounds__(256) void out_kernel(
    const float4* __restrict__ X4,
    float4* __restrict__ out4)
{
    const int STRIDE_T = N_NODE * (D_HID / 4);  // 131072 float4 per snapshot
    int idx = blockIdx.x * 256 + threadIdx.x;
    int n = (idx >> 6) & (N_NODE - 1);
    int i = idx >> 17;

    if (i < WIN) {
        out4[idx] = X4[idx];
    } else {
        int base = (i - 3) * N_NODE + n;
        float p0 = g_p[base];
        float p1 = g_p[base + N_NODE];
        float p2 = g_p[base + 2 * N_NODE];
        float4 a = X4[idx - 3 * STRIDE_T];
        float4 b = X4[idx - 2 * STRIDE_T];
        float4 c = X4[idx - 1 * STRIDE_T];
        float4 o;
        o.x = p0 * a.x + p1 * b.x + p2 * c.x;
        o.y = p0 * a.y + p1 * b.y + p2 * c.y;
        o.z = p0 * a.z + p1 * b.z + p2 * c.z;
        o.w = p0 * a.w + p1 * b.w + p2 * c.w;
        out4[idx] = o;
    }
}

// ---------------------------------------------------------------------------
extern "C" void kernel_launch(void* const* d_in, const int* in_sizes, int n_in,
                              void* d_out, int out_size)
{
    const float* X    = (const float*)d_in[0];  // (128, 2048, 256)
    const float* W    = (const float*)d_in[1];  // (256, 256)
    const float* proj = (const float*)d_in[2];  // (256, 1)
    float* out        = (float*)d_out;

    score_kernel<<<ROWS / 64, 256>>>(
        (const float4*)X, (const float4*)W, proj);
    softmax_kernel<<<T_SNAP, 256>>>();
    out_kernel<<<(ROWS * (D_HID / 4)) / 256, 256>>>(
        (const float4*)X, (float4*)out);
}

// round 4
// speedup vs baseline: 3.0270x; 1.2374x over previous
#include <cuda_runtime.h>
#include <cuda_bf16.h>
#include <cstdint>

// Problem constants (fixed by setup_inputs): T=128, N=2048, D=256, w=3
#define T_SNAP 128
#define N_NODE 2048
#define D_HID  256
#define WIN    3
#define ROWS   (T_SNAP * N_NODE)   // 262144

// Scratch (allocation-free rule: __device__ globals)
__device__ float g_score[ROWS];
__device__ float g_p[ROWS];

// ---------------------------------------------------------------------------
__device__ __forceinline__ uint32_t pack_bf16(float lo, float hi) {
    __nv_bfloat162 h = __floats2bfloat162_rn(lo, hi);   // .x = lo (k), .y = hi (k+1)
    return *reinterpret_cast<uint32_t*>(&h);
}

__device__ __forceinline__ void mma_bf16(float* c, const uint32_t* a, const uint32_t* b) {
    asm volatile(
        "mma.sync.aligned.m16n8k16.row.col.f32.bf16.bf16.f32 "
        "{%0,%1,%2,%3}, {%4,%5,%6,%7}, {%8,%9}, {%0,%1,%2,%3};"
        : "+f"(c[0]), "+f"(c[1]), "+f"(c[2]), "+f"(c[3])
        : "r"(a[0]), "r"(a[1]), "r"(a[2]), "r"(a[3]), "r"(b[0]), "r"(b[1]));
}

// ---------------------------------------------------------------------------
// Kernel 1 (mma.sync bf16 m16n8k16): score[row] = proj . tanh( X[row,:] @ W )
// Block: 256 threads = 8 warps in 2(M) x 4(N). Block tile M=64, N=256, BK=32.
// Smem holds bf16x2-packed tiles: As[m][k/2] (stride 20 u32, conflict-free
// fragment reads), Bs[k/2][n] (stride 264 u32, conflict-free).
// ---------------------------------------------------------------------------
#define AS_STRIDE 20    // u32 per A row (16 data + 4 pad): banks (20r+q)%32 all distinct
#define BS_STRIDE 264   // u32 per B row (256 data + 8 pad): banks (8*qlane+qid)%32 distinct

__global__ __launch_bounds__(256, 2) void score_kernel(
    const float4* __restrict__ X4,
    const float4* __restrict__ W4,
    const float*  __restrict__ proj)
{
    __shared__ uint32_t As[64 * AS_STRIDE];    // 5 KB
    __shared__ uint32_t Bs[16 * BS_STRIDE];    // 16.5 KB
    __shared__ float sproj[D_HID];
    __shared__ float part[4][64];

    const int tid    = threadIdx.x;
    const int lane   = tid & 31;
    const int wid    = tid >> 5;
    const int warp_m = wid >> 2;               // 0..1
    const int warp_n = wid & 3;                // 0..3
    const int qid    = lane >> 2;              // 0..7
    const int qlane  = lane & 3;               // 0..3
    const int row0   = blockIdx.x * 64;

    sproj[tid] = proj[tid];

    float acc[2][8][4];
    #pragma unroll
    for (int mt = 0; mt < 2; mt++)
        #pragma unroll
        for (int nt = 0; nt < 8; nt++)
            #pragma unroll
            for (int i = 0; i < 4; i++) acc[mt][nt][i] = 0.0f;

    #pragma unroll 1
    for (int c = 0; c < 8; ++c) {
        // A chunk: 64 rows x 32 k -> bf16x2 pairs. 2 float4 per thread.
        #pragma unroll
        for (int i = 0; i < 2; i++) {
            int l4 = tid + i * 256;
            int m  = l4 >> 3;
            int c4 = l4 & 7;
            float4 v = X4[(row0 + m) * 64 + c * 8 + c4];
            uint2 u;
            u.x = pack_bf16(v.x, v.y);
            u.y = pack_bf16(v.z, v.w);
            *reinterpret_cast<uint2*>(&As[m * AS_STRIDE + c4 * 2]) = u;
        }
        // B chunk: 32 k x 256 n -> Bs[k2][n] = {W[2k2][n], W[2k2+1][n]}.
        // 4 groups per thread; each group: 2 float4 reads (rows k, k+1), uint4 write.
        #pragma unroll
        for (int i = 0; i < 4; i++) {
            int g  = tid + i * 256;
            int k2 = g >> 6;
            int ng = g & 63;
            float4 f0 = W4[(c * 32 + k2 * 2)     * 64 + ng];
            float4 f1 = W4[(c * 32 + k2 * 2 + 1) * 64 + ng];
            uint4 u;
            u.x = pack_bf16(f0.x, f1.x);
            u.y = pack_bf16(f0.y, f1.y);
            u.z = pack_bf16(f0.z, f1.z);
            u.w = pack_bf16(f0.w, f1.w);
            *reinterpret_cast<uint4*>(&Bs[k2 * BS_STRIDE + ng * 4]) = u;
        }
        __syncthreads();

        #pragma unroll
        for (int ks = 0; ks < 2; ks++) {       // two k16 steps per 32-K chunk
            const int k2b = ks * 8;
            uint32_t a[2][4];
            #pragma unroll
            for (int mt = 0; mt < 2; mt++) {
                int r = warp_m * 32 + mt * 16 + qid;
                a[mt][0] = As[r * AS_STRIDE + k2b + qlane];
                a[mt][1] = As[(r + 8) * AS_STRIDE + k2b + qlane];
                a[mt][2] = As[r * AS_STRIDE + k2b + qlane + 4];
                a[mt][3] = As[(r + 8) * AS_STRIDE + k2b + qlane + 4];
            }
            uint32_t b[8][2];
            #pragma unroll
            for (int nt = 0; nt < 8; nt++) {
                int n = warp_n * 64 + nt * 8 + qid;
                b[nt][0] = Bs[(k2b + qlane)     * BS_STRIDE + n];
                b[nt][1] = Bs[(k2b + qlane + 4) * BS_STRIDE + n];
            }
            #pragma unroll
            for (int mt = 0; mt < 2; mt++)
                #pragma unroll
                for (int nt = 0; nt < 8; nt++)
                    mma_bf16(acc[mt][nt], a[mt], b[nt]);
        }
        __syncthreads();
    }

    // Fused epilogue: per-row sum of tanh(u)*proj over this warp's 64 cols.
    float psum[2][2];
    psum[0][0] = psum[0][1] = psum[1][0] = psum[1][1] = 0.0f;
    #pragma unroll
    for (int mt = 0; mt < 2; mt++)
        #pragma unroll
        for (int nt = 0; nt < 8; nt++) {
            int cb = warp_n * 64 + nt * 8 + 2 * qlane;
            float p0 = sproj[cb], p1 = sproj[cb + 1];
            psum[mt][0] += tanhf(acc[mt][nt][0]) * p0 + tanhf(acc[mt][nt][1]) * p1;
            psum[mt][1] += tanhf(acc[mt][nt][2]) * p0 + tanhf(acc[mt][nt][3]) * p1;
        }
    #pragma unroll
    for (int off = 1; off < 4; off <<= 1) {
        #pragma unroll
        for (int mt = 0; mt < 2; mt++) {
            psum[mt][0] += __shfl_xor_sync(0xffffffffu, psum[mt][0], off);
            psum[mt][1] += __shfl_xor_sync(0xffffffffu, psum[mt][1], off);
        }
    }
    if (qlane == 0) {
        #pragma unroll
        for (int mt = 0; mt < 2; mt++) {
            part[warp_n][warp_m * 32 + mt * 16 + qid]     = psum[mt][0];
            part[warp_n][warp_m * 32 + mt * 16 + qid + 8] = psum[mt][1];
        }
    }
    __syncthreads();
    if (tid < 64)
        g_score[row0 + tid] =
            part[0][tid] + part[1][tid] + part[2][tid] + part[3][tid];
}

// ---------------------------------------------------------------------------
// Kernel 2: p[j,:] = softmax over N of score[j,:]   (one block per row j)
// ---------------------------------------------------------------------------
__global__ __launch_bounds__(256) void softmax_kernel()
{
    __shared__ float red_max[8];
    __shared__ float red_sum[8];
    const int j   = blockIdx.x;
    const int tid = threadIdx.x;
    const float* row = g_score + j * N_NODE;

    float v[8];
    float m = -1e30f;
    #pragma unroll
    for (int i = 0; i < 8; i++) {
        v[i] = row[tid + i * 256];
        m = fmaxf(m, v[i]);
    }
    #pragma unroll
    for (int off = 16; off > 0; off >>= 1)
        m = fmaxf(m, __shfl_xor_sync(0xffffffffu, m, off));
    if ((tid & 31) == 0) red_max[tid >> 5] = m;
    __syncthreads();
    float bm = red_max[0];
    #pragma unroll
    for (int wq = 1; wq < 8; wq++) bm = fmaxf(bm, red_max[wq]);

    float s = 0.0f;
    #pragma unroll
    for (int i = 0; i < 8; i++) {
        v[i] = expf(v[i] - bm);
        s += v[i];
    }
    #pragma unroll
    for (int off = 16; off > 0; off >>= 1)
        s += __shfl_xor_sync(0xffffffffu, s, off);
    if ((tid & 31) == 0) red_sum[tid >> 5] = s;
    __syncthreads();
    float bs = 0.0f;
    #pragma unroll
    for (int wq = 0; wq < 8; wq++) bs += red_sum[wq];
    float inv = 1.0f / bs;

    #pragma unroll
    for (int i = 0; i < 8; i++)
        g_p[j * N_NODE + tid + i * 256] = v[i] * inv;
}

// ---------------------------------------------------------------------------
// Kernel 3: out[i,n,:] = X[i,n,:] for i<3, else
//           sum_{k=1..3} p[i-k,n] * X[i-k,n,:]    (float4-vectorized stream)
// ---------------------------------------------------------------------------
__global__ __launch_bounds__(256) void out_kernel(
    const float4* __restrict__ X4,
    float4* __restrict__ out4)
{
    const int STRIDE_T = N_NODE * (D_HID / 4);  // 131072 float4 per snapshot
    int idx = blockIdx.x * 256 + threadIdx.x;
    int n = (idx >> 6) & (N_NODE - 1);
    int i = idx >> 17;

    if (i < WIN) {
        out4[idx] = X4[idx];
    } else {
        int base = (i - 3) * N_NODE + n;
        float p0 = g_p[base];
        float p1 = g_p[base + N_NODE];
        float p2 = g_p[base + 2 * N_NODE];
        float4 a = X4[idx - 3 * STRIDE_T];
        float4 b = X4[idx - 2 * STRIDE_T];
        float4 c = X4[idx - 1 * STRIDE_T];
        float4 o;
        o.x = p0 * a.x + p1 * b.x + p2 * c.x;
        o.y = p0 * a.y + p1 * b.y + p2 * c.y;
        o.z = p0 * a.z + p1 * b.z + p2 * c.z;
        o.w = p0 * a.w + p1 * b.w + p2 * c.w;
        out4[idx] = o;
    }
}

// ---------------------------------------------------------------------------
extern "C" void kernel_launch(void* const* d_in, const int* in_sizes, int n_in,
                              void* d_out, int out_size)
{
    const float* X    = (const float*)d_in[0];  // (128, 2048, 256)
    const float* W    = (const float*)d_in[1];  // (256, 256)
    const float* proj = (const float*)d_in[2];  // (256, 1)
    float* out        = (float*)d_out;

    score_kernel<<<ROWS / 64, 256>>>(
        (const float4*)X, (const float4*)W, proj);
    softmax_kernel<<<T_SNAP, 256>>>();
    out_kernel<<<(ROWS * (D_HID / 4)) / 256, 256>>>(
        (const float4*)X, (float4*)out);
}

// round 5
// speedup vs baseline: 3.8359x; 1.2672x over previous
#include <cuda_runtime.h>
#include <cuda_bf16.h>
#include <cstdint>

// Problem constants (fixed by setup_inputs): T=128, N=2048, D=256, w=3
#define T_SNAP 128
#define N_NODE 2048
#define D_HID  256
#define WIN    3
#define ROWS   (T_SNAP * N_NODE)   // 262144

// Scratch (allocation-free rule: __device__ globals)
__device__ float g_score[ROWS];
__device__ float g_p[ROWS];
// Pre-packed W: g_Wb[(c*16 + k2)*256 + n] = bf16x2{ W[32c+2k2][n], W[32c+2k2+1][n] }
__device__ uint32_t g_Wb[8 * 16 * 256];   // 128 KB

// ---------------------------------------------------------------------------
__device__ __forceinline__ uint32_t pack_bf16(float lo, float hi) {
    __nv_bfloat162 h = __floats2bfloat162_rn(lo, hi);
    return *reinterpret_cast<uint32_t*>(&h);
}

__device__ __forceinline__ void mma_bf16(float* c, const uint32_t* a, const uint32_t* b) {
    asm volatile(
        "mma.sync.aligned.m16n8k16.row.col.f32.bf16.bf16.f32 "
        "{%0,%1,%2,%3}, {%4,%5,%6,%7}, {%8,%9}, {%0,%1,%2,%3};"
        : "+f"(c[0]), "+f"(c[1]), "+f"(c[2]), "+f"(c[3])
        : "r"(a[0]), "r"(a[1]), "r"(a[2]), "r"(a[3]), "r"(b[0]), "r"(b[1]));
}

__device__ __forceinline__ void cp_async16(uint32_t smem_dst, const void* gptr) {
    asm volatile("cp.async.cg.shared.global [%0], [%1], 16;"
                 :: "r"(smem_dst), "l"(gptr) : "memory");
}
__device__ __forceinline__ void cp_commit() {
    asm volatile("cp.async.commit_group;" ::: "memory");
}
__device__ __forceinline__ void cp_wait_all() {
    asm volatile("cp.async.wait_group 0;" ::: "memory");
}

// ---------------------------------------------------------------------------
// Kernel 0: pack W into bf16x2 chunk layout (one-shot, ~µs)
// ---------------------------------------------------------------------------
__global__ __launch_bounds__(256) void prep_w_kernel(const float* __restrict__ W)
{
    int idx = blockIdx.x * 256 + threadIdx.x;  // 0..32767
    int n  = idx & 255;
    int kk = idx >> 8;                         // global k-pair 0..127
    g_Wb[idx] = pack_bf16(W[(2 * kk) * D_HID + n], W[(2 * kk + 1) * D_HID + n]);
}

// ---------------------------------------------------------------------------
// Kernel 1 (mma.sync bf16, pipelined): score[row] = proj . tanh(X[row,:] @ W)
// Block: 256 threads = 8 warps, 2(M) x 4(N). Tile M=64, N=256, BK=32 x 8.
// Double-buffered smem; B arrives by cp.async from pre-packed g_Wb; A is
// LDG-prefetched into regs, converted, STS'd while MMAs run on the other buf.
// ---------------------------------------------------------------------------
#define AS_STRIDE 20    // u32: banks (20*qid+qlane)%32 all distinct
#define BS_STRIDE 264   // u32: banks (8*qlane+qid)%32 all distinct

__global__ __launch_bounds__(256, 2) void score_kernel(
    const float4* __restrict__ X4,
    const float*  __restrict__ proj)
{
    __shared__ uint32_t As[2][64 * AS_STRIDE];   // 10 KB
    __shared__ uint32_t Bs[2][16 * BS_STRIDE];   // 33.8 KB
    __shared__ float sproj[D_HID];
    __shared__ float part[4][64];

    const int tid    = threadIdx.x;
    const int lane   = tid & 31;
    const int wid    = tid >> 5;
    const int warp_m = wid >> 2;
    const int warp_n = wid & 3;
    const int qid    = lane >> 2;
    const int qlane  = lane & 3;
    const int row0   = blockIdx.x * 64;

    sproj[tid] = proj[tid];

    // Per-thread fixed load coordinates
    const int am0 = tid >> 3;            // A row for segment 0
    const int ac0 = tid & 7;             // A float4-col for segment 0
    const int am1 = (tid + 256) >> 3;
    const int ac1 = (tid + 256) & 7;

    float acc[2][8][4];
    #pragma unroll
    for (int mt = 0; mt < 2; mt++)
        #pragma unroll
        for (int nt = 0; nt < 8; nt++)
            #pragma unroll
            for (int i = 0; i < 4; i++) acc[mt][nt][i] = 0.0f;

    // ---- Prologue: stage chunk 0 ----
    float4 pa0 = X4[(row0 + am0) * 64 + ac0];
    float4 pa1 = X4[(row0 + am1) * 64 + ac1];
    #pragma unroll
    for (int i = 0; i < 4; i++) {
        int seg = tid + i * 256;         // 0..1023
        int k2  = seg >> 6;
        int ng  = seg & 63;
        uint32_t dst = (uint32_t)__cvta_generic_to_shared(&Bs[0][k2 * BS_STRIDE + ng * 4]);
        cp_async16(dst, &g_Wb[k2 * 256 + ng * 4]);
    }
    cp_commit();
    {
        uint2 u0, u1;
        u0.x = pack_bf16(pa0.x, pa0.y); u0.y = pack_bf16(pa0.z, pa0.w);
        u1.x = pack_bf16(pa1.x, pa1.y); u1.y = pack_bf16(pa1.z, pa1.w);
        *reinterpret_cast<uint2*>(&As[0][am0 * AS_STRIDE + ac0 * 2]) = u0;
        *reinterpret_cast<uint2*>(&As[0][am1 * AS_STRIDE + ac1 * 2]) = u1;
    }
    cp_wait_all();
    __syncthreads();

    #pragma unroll 1
    for (int c = 0; c < 8; ++c) {
        const int buf = c & 1;
        const int nxt = buf ^ 1;

        // Stage chunk c+1: B via cp.async, A via LDG prefetch
        if (c < 7) {
            #pragma unroll
            for (int i = 0; i < 4; i++) {
                int seg = tid + i * 256;
                int k2  = seg >> 6;
                int ng  = seg & 63;
                uint32_t dst = (uint32_t)__cvta_generic_to_shared(
                    &Bs[nxt][k2 * BS_STRIDE + ng * 4]);
                cp_async16(dst, &g_Wb[((c + 1) * 16 + k2) * 256 + ng * 4]);
            }
            cp_commit();
            pa0 = X4[(row0 + am0) * 64 + (c + 1) * 8 + ac0];
            pa1 = X4[(row0 + am1) * 64 + (c + 1) * 8 + ac1];
        }

        // MMAs on current buffer
        const uint32_t* Ab = As[buf];
        const uint32_t* Bb = Bs[buf];
        #pragma unroll
        for (int ks = 0; ks < 2; ks++) {
            const int k2b = ks * 8;
            uint32_t a[2][4];
            #pragma unroll
            for (int mt = 0; mt < 2; mt++) {
                int r = warp_m * 32 + mt * 16 + qid;
                a[mt][0] = Ab[r * AS_STRIDE + k2b + qlane];
                a[mt][1] = Ab[(r + 8) * AS_STRIDE + k2b + qlane];
                a[mt][2] = Ab[r * AS_STRIDE + k2b + qlane + 4];
                a[mt][3] = Ab[(r + 8) * AS_STRIDE + k2b + qlane + 4];
            }
            uint32_t b[8][2];
            #pragma unroll
            for (int nt = 0; nt < 8; nt++) {
                int n = warp_n * 64 + nt * 8 + qid;
                b[nt][0] = Bb[(k2b + qlane)     * BS_STRIDE + n];
                b[nt][1] = Bb[(k2b + qlane + 4) * BS_STRIDE + n];
            }
            #pragma unroll
            for (int mt = 0; mt < 2; mt++)
                #pragma unroll
                for (int nt = 0; nt < 8; nt++)
                    mma_bf16(acc[mt][nt], a[mt], b[nt]);
        }

        if (c < 7) {
            uint2 u0, u1;
            u0.x = pack_bf16(pa0.x, pa0.y); u0.y = pack_bf16(pa0.z, pa0.w);
            u1.x = pack_bf16(pa1.x, pa1.y); u1.y = pack_bf16(pa1.z, pa1.w);
            *reinterpret_cast<uint2*>(&As[nxt][am0 * AS_STRIDE + ac0 * 2]) = u0;
            *reinterpret_cast<uint2*>(&As[nxt][am1 * AS_STRIDE + ac1 * 2]) = u1;
            cp_wait_all();
            __syncthreads();
        }
    }

    // Fused epilogue: per-row sum of tanh(u)*proj over this warp's 64 cols.
    float psum[2][2];
    psum[0][0] = psum[0][1] = psum[1][0] = psum[1][1] = 0.0f;
    #pragma unroll
    for (int mt = 0; mt < 2; mt++)
        #pragma unroll
        for (int nt = 0; nt < 8; nt++) {
            int cb = warp_n * 64 + nt * 8 + 2 * qlane;
            float p0 = sproj[cb], p1 = sproj[cb + 1];
            psum[mt][0] += tanhf(acc[mt][nt][0]) * p0 + tanhf(acc[mt][nt][1]) * p1;
            psum[mt][1] += tanhf(acc[mt][nt][2]) * p0 + tanhf(acc[mt][nt][3]) * p1;
        }
    #pragma unroll
    for (int off = 1; off < 4; off <<= 1) {
        #pragma unroll
        for (int mt = 0; mt < 2; mt++) {
            psum[mt][0] += __shfl_xor_sync(0xffffffffu, psum[mt][0], off);
            psum[mt][1] += __shfl_xor_sync(0xffffffffu, psum[mt][1], off);
        }
    }
    if (qlane == 0) {
        #pragma unroll
        for (int mt = 0; mt < 2; mt++) {
            part[warp_n][warp_m * 32 + mt * 16 + qid]     = psum[mt][0];
            part[warp_n][warp_m * 32 + mt * 16 + qid + 8] = psum[mt][1];
        }
    }
    __syncthreads();
    if (tid < 64)
        g_score[row0 + tid] =
            part[0][tid] + part[1][tid] + part[2][tid] + part[3][tid];
}

// ---------------------------------------------------------------------------
// Kernel 2: p[j,:] = softmax over N of score[j,:]   (one block per row j)
// ---------------------------------------------------------------------------
__global__ __launch_bounds__(256) void softmax_kernel()
{
    __shared__ float red_max[8];
    __shared__ float red_sum[8];
    const int j   = blockIdx.x;
    const int tid = threadIdx.x;
    const float* row = g_score + j * N_NODE;

    float v[8];
    float m = -1e30f;
    #pragma unroll
    for (int i = 0; i < 8; i++) {
        v[i] = row[tid + i * 256];
        m = fmaxf(m, v[i]);
    }
    #pragma unroll
    for (int off = 16; off > 0; off >>= 1)
        m = fmaxf(m, __shfl_xor_sync(0xffffffffu, m, off));
    if ((tid & 31) == 0) red_max[tid >> 5] = m;
    __syncthreads();
    float bm = red_max[0];
    #pragma unroll
    for (int wq = 1; wq < 8; wq++) bm = fmaxf(bm, red_max[wq]);

    float s = 0.0f;
    #pragma unroll
    for (int i = 0; i < 8; i++) {
        v[i] = expf(v[i] - bm);
        s += v[i];
    }
    #pragma unroll
    for (int off = 16; off > 0; off >>= 1)
        s += __shfl_xor_sync(0xffffffffu, s, off);
    if ((tid & 31) == 0) red_sum[tid >> 5] = s;
    __syncthreads();
    float bs = 0.0f;
    #pragma unroll
    for (int wq = 0; wq < 8; wq++) bs += red_sum[wq];
    float inv = 1.0f / bs;

    #pragma unroll
    for (int i = 0; i < 8; i++)
        g_p[j * N_NODE + tid + i * 256] = v[i] * inv;
}

// ---------------------------------------------------------------------------
// Kernel 3: out[i,n,:] = X[i,n,:] for i<3, else
//           sum_{k=1..3} p[i-k,n] * X[i-k,n,:]    (float4-vectorized stream)
// ---------------------------------------------------------------------------
__global__ __launch_bounds__(256) void out_kernel(
    const float4* __restrict__ X4,
    float4* __restrict__ out4)
{
    const int STRIDE_T = N_NODE * (D_HID / 4);  // 131072 float4 per snapshot
    int idx = blockIdx.x * 256 + threadIdx.x;
    int n = (idx >> 6) & (N_NODE - 1);
    int i = idx >> 17;

    if (i < WIN) {
        out4[idx] = X4[idx];
    } else {
        int base = (i - 3) * N_NODE + n;
        float p0 = g_p[base];
        float p1 = g_p[base + N_NODE];
        float p2 = g_p[base + 2 * N_NODE];
        float4 a = X4[idx - 3 * STRIDE_T];
        float4 b = X4[idx - 2 * STRIDE_T];
        float4 c = X4[idx - 1 * STRIDE_T];
        float4 o;
        o.x = p0 * a.x + p1 * b.x + p2 * c.x;
        o.y = p0 * a.y + p1 * b.y + p2 * c.y;
        o.z = p0 * a.z + p1 * b.z + p2 * c.z;
        o.w = p0 * a.w + p1 * b.w + p2 * c.w;
        out4[idx] = o;
    }
}

// ---------------------------------------------------------------------------
extern "C" void kernel_launch(void* const* d_in, const int* in_sizes, int n_in,
                              void* d_out, int out_size)
{
    const float* X    = (const float*)d_in[0];  // (128, 2048, 256)
    const float* W    = (const float*)d_in[1];  // (256, 256)
    const float* proj = (const float*)d_in[2];  // (256, 1)
    float* out        = (float*)d_out;

    prep_w_kernel<<<128, 256>>>(W);
    score_kernel<<<ROWS / 64, 256>>>((const float4*)X, proj);
    softmax_kernel<<<T_SNAP, 256>>>();
    out_kernel<<<(ROWS * (D_HID / 4)) / 256, 256>>>(
        (const float4*)X, (float4*)out);
}